// round 7
// baseline (speedup 1.0000x reference)
#include <cuda_runtime.h>
#include <math.h>

#define N_K   256
#define N_T   128
#define N_C   32
#define N_D   10
#define N_SPK 1000000
#define LOG2PI 1.8378770664093453f

// Packed coefficient row per component (68 floats = 34 f32-pairs = 272B, 16B aligned):
// [0..54]  quad coeffs over upper-tri features s_i*s_j (i<=j): -P_ii/2 diag, -P_ij off-diag
// [55]     0 (pad feature slot)
// [56..65] linear coeffs (P @ mu)
// [66]     const K_c = -0.5*(mu'P mu + logdet + D*log2pi)
// [67]     0
#define ROWF 68
#define ROWP 34            // u64 pairs per row

#define MAIN_BLOCK 256
#define NBLOCKS ((N_SPK + MAIN_BLOCK - 1) / MAIN_BLOCK)

typedef unsigned long long u64;

__device__ __align__(16) u64 g_W[N_C * ROWP];
__device__ float g_prior;
__device__ float g_logpi[N_K * N_T * N_C];   // (k,t,c)-major, 4 MB, L2-resident
__device__ float g_partial[NBLOCKS];
__device__ unsigned int g_count;

// ---- f32x2 packed-math helpers (Blackwell dual-fp32 pipe, PTX-only) ----
__device__ __forceinline__ u64 pk2(float lo, float hi) {
    u64 r; asm("mov.b64 %0,{%1,%2};" : "=l"(r) : "f"(lo), "f"(hi)); return r;
}
__device__ __forceinline__ void fma2(u64& d, u64 a, u64 b) {
    asm("fma.rn.f32x2 %0,%1,%2,%3;" : "=l"(d) : "l"(a), "l"(b), "l"(d));
}
__device__ __forceinline__ u64 add2(u64 a, u64 b) {
    u64 r; asm("add.rn.f32x2 %0,%1,%2;" : "=l"(r) : "l"(a), "l"(b)); return r;
}
__device__ __forceinline__ float2 upk(u64 a) {
    float2 v; asm("mov.b64 {%0,%1},%2;" : "=f"(v.x), "=f"(v.y) : "l"(a)); return v;
}

// ---------------------------------------------------------------------------
// Kernel 1: log_pi table (warp per (k,t), lane = component), PLUS one extra
// block (blockIdx == gridDim-1) doing the per-component Cholesky -> packed
// coefficients, the closed-form prior term, and the g_count reset.
// ---------------------------------------------------------------------------
__global__ void logpi_setup_kernel(const float* __restrict__ y,
                                   const float* __restrict__ b_mu,
                                   const float* __restrict__ beta_mu,
                                   const float* __restrict__ means,
                                   const float* __restrict__ covs,
                                   const float* __restrict__ b_log_sig,
                                   const float* __restrict__ beta_log_sig) {
    if (blockIdx.x == gridDim.x - 1) {
        // ---- setup block ----
        int tid = threadIdx.x;
        if (tid == 0) g_count = 0;

        if (tid < N_C) {
            const float* cov = covs + tid * N_D * N_D;
            const float* mu  = means + tid * N_D;

            float L[N_D][N_D];
            float logdet = 0.0f;
            for (int j = 0; j < N_D; j++) {
                float sdiag = cov[j * N_D + j];
                for (int k = 0; k < j; k++) sdiag -= L[j][k] * L[j][k];
                float d = sqrtf(sdiag);
                L[j][j] = d;
                logdet += 2.0f * logf(d);
                for (int i = j + 1; i < N_D; i++) {
                    float v = cov[i * N_D + j];
                    for (int k = 0; k < j; k++) v -= L[i][k] * L[j][k];
                    L[i][j] = v / d;
                }
            }
            float Li[N_D][N_D];
            for (int j = 0; j < N_D; j++)
                for (int i = 0; i < N_D; i++) {
                    if (i < j) { Li[i][j] = 0.0f; continue; }
                    float v = (i == j) ? 1.0f : 0.0f;
                    for (int k = j; k < i; k++) v -= L[i][k] * Li[k][j];
                    Li[i][j] = v / L[i][i];
                }
            float P[N_D][N_D];
            for (int i = 0; i < N_D; i++)
                for (int j = 0; j < N_D; j++) {
                    float v = 0.0f;
                    int k0 = (i > j) ? i : j;
                    for (int k = k0; k < N_D; k++) v += Li[k][i] * Li[k][j];
                    P[i][j] = v;
                }
            float w[N_D], quad = 0.0f;
            for (int i = 0; i < N_D; i++) {
                float v = 0.0f;
                for (int j = 0; j < N_D; j++) v += P[i][j] * mu[j];
                w[i] = v;
                quad += v * mu[i];
            }
            float* Wc = (float*)g_W + tid * ROWF;
            int u = 0;
            for (int i = 0; i < N_D; i++)
                for (int j = i; j < N_D; j++)
                    Wc[u++] = (i == j) ? (-0.5f * P[i][i]) : (-P[i][j]);
            Wc[55] = 0.0f;
            for (int i = 0; i < N_D; i++) Wc[56 + i] = w[i];
            Wc[66] = -0.5f * (quad + logdet + (float)N_D * LOG2PI);
            Wc[67] = 0.0f;
        }

        __shared__ float red[256];
        float acc = 0.0f;
        for (int i = tid; i < N_C; i += 256)
            acc += b_log_sig[i] - 0.5f * b_mu[i] * b_mu[i];
        for (int i = tid; i < N_C * N_T; i += 256)
            acc += beta_log_sig[i] - 0.5f * beta_mu[i] * beta_mu[i];
        red[tid] = acc;
        __syncthreads();
        for (int s2 = 128; s2 > 0; s2 >>= 1) {
            if (tid < s2) red[tid] += red[tid + s2];
            __syncthreads();
        }
        if (tid == 0) g_prior = red[0];
        return;
    }

    // ---- logpi blocks ----
    int warp = (blockIdx.x * blockDim.x + threadIdx.x) >> 5;
    int lane = threadIdx.x & 31;
    if (warp >= N_K * N_T) return;
    int k = warp >> 7;          // N_T = 128
    int t = warp & (N_T - 1);

    float yv  = __ldg(&y[k * N_T + t]);
    float lam = __ldg(&b_mu[lane]) + __ldg(&beta_mu[lane * N_T + t]) * yv;

    float m = lam;
    #pragma unroll
    for (int o = 16; o > 0; o >>= 1)
        m = fmaxf(m, __shfl_xor_sync(0xffffffffu, m, o));
    float e = __expf(lam - m);
    float ssum = e;
    #pragma unroll
    for (int o = 16; o > 0; o >>= 1)
        ssum += __shfl_xor_sync(0xffffffffu, ssum, o);

    g_logpi[warp * N_C + lane] = lam - m - __logf(ssum);
}

// ---------------------------------------------------------------------------
// Kernel 2: main — thread per spike. 55 quadratic features packed directly
// into 28 f32x2 pairs; 32 components x 33 fma.rn.f32x2 with W streamed from
// SMEM via LDS.128 broadcast (17 loads/component). Streaming LSE, block tree
// reduce, last-block deterministic final reduction (double).
// ---------------------------------------------------------------------------
__global__ void __launch_bounds__(MAIN_BLOCK)
main_kernel(const float* __restrict__ s,
            const int*   __restrict__ ks,
            const int*   __restrict__ ts,
            float*       __restrict__ out) {
    __shared__ __align__(16) u64 sW[N_C * ROWP];
    __shared__ float sred[MAIN_BLOCK];
    __shared__ unsigned int s_isLast;

    for (int i = threadIdx.x; i < N_C * ROWP; i += MAIN_BLOCK)
        sW[i] = g_W[i];
    __syncthreads();

    int n = blockIdx.x * MAIN_BLOCK + threadIdx.x;
    float lse = 0.0f;

    if (n < N_SPK) {
        float sv[N_D];
        #pragma unroll
        for (int i = 0; i < N_D; i++) sv[i] = __ldg(&s[n * N_D + i]);

        // 55 upper-tri features (s_i*s_j, i<=j, row-major) + 1 zero pad,
        // packed straight into 28 f32x2 pairs (no float staging array).
        u64 pf[28];
        {
            float lo = 0.0f;
            int u = 0;
            #pragma unroll
            for (int i = 0; i < N_D; i++) {
                #pragma unroll
                for (int j = i; j < N_D; j++) {
                    float v = sv[i] * sv[j];
                    if (u & 1) pf[u >> 1] = pk2(lo, v);
                    else       lo = v;
                    u++;
                }
            }
            pf[27] = pk2(lo, 0.0f);   // feature 54 + pad
        }
        u64 ps[5];
        #pragma unroll
        for (int p = 0; p < 5; p++) ps[p] = pk2(sv[2 * p], sv[2 * p + 1]);

        const float* lp = g_logpi + ((size_t)(__ldg(&ks[n]) * N_T + __ldg(&ts[n]))) * N_C;

        float m = -1e30f, ssum = 0.0f;
        #pragma unroll 2
        for (int c = 0; c < N_C; c++) {
            const ulonglong2* w2 = reinterpret_cast<const ulonglong2*>(sW + c * ROWP);
            u64 a0 = 0ull, a1 = 0ull, a2 = 0ull, a3 = 0ull;
            // quad pairs 0..27 via 14 x LDS.128 (broadcast)
            #pragma unroll
            for (int p = 0; p < 14; p++) {
                ulonglong2 w = w2[p];
                fma2(a0, w.x, pf[2 * p]);
                fma2(a1, w.y, pf[2 * p + 1]);
            }
            // linear pairs 28..32 + const (pair 33 lo)
            ulonglong2 wa = w2[14];
            fma2(a2, wa.x, ps[0]); fma2(a3, wa.y, ps[1]);
            ulonglong2 wb = w2[15];
            fma2(a2, wb.x, ps[2]); fma2(a3, wb.y, ps[3]);
            ulonglong2 wc = w2[16];
            fma2(a2, wc.x, ps[4]);
            float2 kc = upk(wc.y);

            float2 q = upk(add2(add2(a0, a1), add2(a2, a3)));
            float logit = (q.x + q.y) + kc.x + __ldg(&lp[c]);

            float nm = fmaxf(m, logit);
            ssum = ssum * __expf(m - nm) + __expf(logit - nm);
            m = nm;
        }
        lse = m + __logf(ssum);
    }

    sred[threadIdx.x] = lse;
    __syncthreads();
    #pragma unroll
    for (int s2 = MAIN_BLOCK / 2; s2 > 0; s2 >>= 1) {
        if (threadIdx.x < s2) sred[threadIdx.x] += sred[threadIdx.x + s2];
        __syncthreads();
    }
    if (threadIdx.x == 0) {
        g_partial[blockIdx.x] = sred[0];
        __threadfence();
        unsigned int prev = atomicAdd(&g_count, 1u);
        s_isLast = (prev == (unsigned int)(NBLOCKS - 1)) ? 1u : 0u;
    }
    __syncthreads();

    if (s_isLast) {
        // Deterministic final reduce: fixed-order strided double sums + fixed tree.
        __shared__ double dred[MAIN_BLOCK];
        const volatile float* vp = g_partial;
        double acc = 0.0;
        for (int i = threadIdx.x; i < NBLOCKS; i += MAIN_BLOCK)
            acc += (double)vp[i];
        dred[threadIdx.x] = acc;
        __syncthreads();
        for (int s2 = MAIN_BLOCK / 2; s2 > 0; s2 >>= 1) {
            if (threadIdx.x < s2) dred[threadIdx.x] += dred[threadIdx.x + s2];
            __syncthreads();
        }
        if (threadIdx.x == 0) out[0] = (float)(dred[0] + (double)g_prior);
    }
}

// ---------------------------------------------------------------------------
extern "C" void kernel_launch(void* const* d_in, const int* in_sizes, int n_in,
                              void* d_out, int out_size) {
    const float* s            = (const float*)d_in[0];
    const float* y            = (const float*)d_in[1];
    const int*   ks           = (const int*)  d_in[2];
    const int*   ts           = (const int*)  d_in[3];
    const float* means        = (const float*)d_in[4];
    const float* covs         = (const float*)d_in[5];
    const float* b_mu         = (const float*)d_in[6];
    const float* b_log_sig    = (const float*)d_in[7];
    const float* beta_mu      = (const float*)d_in[8];
    const float* beta_log_sig = (const float*)d_in[9];

    // logpi: 32768 (k,t) warps -> 4096 blocks of 256; +1 setup block
    logpi_setup_kernel<<<(N_K * N_T * 32) / 256 + 1, 256>>>(
        y, b_mu, beta_mu, means, covs, b_log_sig, beta_log_sig);

    main_kernel<<<NBLOCKS, MAIN_BLOCK>>>(s, ks, ts, (float*)d_out);
}

// round 10
// speedup vs baseline: 1.2960x; 1.2960x over previous
#include <cuda_runtime.h>
#include <math.h>

#define N_K   256
#define N_T   128
#define N_C   32
#define N_D   10
#define N_SPK 1000000
#define LOG2PI 1.8378770664093453f

// Packed coefficient row per component: 34 f32-pairs (68 floats, 272B):
// pairs [0..27]  : quad coeffs over upper-tri features s_i*s_j (i<=j), pad 0 in slot 55
// pairs [28..32] : linear coeffs (P @ mu)
// pair  [33]     : (K_c - M, 0)  -- paired against feature (1, 0)
#define ROWF 68
#define ROWP 34

#define MAIN_BLOCK 128
#define N_HALF (N_SPK / 2)                       // 500000 threads, 2 spikes each
#define NBLOCKS ((N_HALF + MAIN_BLOCK - 1) / MAIN_BLOCK)

typedef unsigned long long u64;

__device__ __align__(16) u64 g_W[N_C * ROWP];
__device__ float g_prior;
__device__ float g_M;                            // global logit upper bound
__device__ float g_logpi[N_K * N_T * N_C];       // (k,t,c)-major, 4 MB, L2-resident
__device__ float g_partial[NBLOCKS];
__device__ unsigned int g_count;

// ---- f32x2 packed-math helpers (Blackwell dual-fp32 pipe, PTX-only) ----
__device__ __forceinline__ u64 pk2(float lo, float hi) {
    u64 r; asm("mov.b64 %0,{%1,%2};" : "=l"(r) : "f"(lo), "f"(hi)); return r;
}
__device__ __forceinline__ void fma2(u64& d, u64 a, u64 b) {
    asm("fma.rn.f32x2 %0,%1,%2,%3;" : "=l"(d) : "l"(a), "l"(b), "l"(d));
}
__device__ __forceinline__ u64 add2(u64 a, u64 b) {
    u64 r; asm("add.rn.f32x2 %0,%1,%2;" : "=l"(r) : "l"(a), "l"(b)); return r;
}
__device__ __forceinline__ float2 upk(u64 a) {
    float2 v; asm("mov.b64 {%0,%1},%2;" : "=f"(v.x), "=f"(v.y) : "l"(a)); return v;
}

// ---------------------------------------------------------------------------
// Kernel 1: log_pi table (warp per (k,t), lane = component), PLUS one extra
// block (blockIdx == gridDim-1): Cholesky -> packed coefficients with the
// global bound M folded in, prior term, g_count reset.
// ---------------------------------------------------------------------------
__global__ void logpi_setup_kernel(const float* __restrict__ y,
                                   const float* __restrict__ b_mu,
                                   const float* __restrict__ beta_mu,
                                   const float* __restrict__ means,
                                   const float* __restrict__ covs,
                                   const float* __restrict__ b_log_sig,
                                   const float* __restrict__ beta_log_sig) {
    if (blockIdx.x == gridDim.x - 1) {
        int tid = threadIdx.x;
        if (tid == 0) g_count = 0;

        if (tid < N_C) {
            const float* cov = covs + tid * N_D * N_D;
            const float* mu  = means + tid * N_D;

            float L[N_D][N_D];
            float logdet = 0.0f;
            for (int j = 0; j < N_D; j++) {
                float sdiag = cov[j * N_D + j];
                for (int k = 0; k < j; k++) sdiag -= L[j][k] * L[j][k];
                float d = sqrtf(sdiag);
                L[j][j] = d;
                logdet += 2.0f * logf(d);
                for (int i = j + 1; i < N_D; i++) {
                    float v = cov[i * N_D + j];
                    for (int k = 0; k < j; k++) v -= L[i][k] * L[j][k];
                    L[i][j] = v / d;
                }
            }
            float Li[N_D][N_D];
            for (int j = 0; j < N_D; j++)
                for (int i = 0; i < N_D; i++) {
                    if (i < j) { Li[i][j] = 0.0f; continue; }
                    float v = (i == j) ? 1.0f : 0.0f;
                    for (int k = j; k < i; k++) v -= L[i][k] * Li[k][j];
                    Li[i][j] = v / L[i][i];
                }
            float P[N_D][N_D];
            for (int i = 0; i < N_D; i++)
                for (int j = 0; j < N_D; j++) {
                    float v = 0.0f;
                    int k0 = (i > j) ? i : j;
                    for (int k = k0; k < N_D; k++) v += Li[k][i] * Li[k][j];
                    P[i][j] = v;
                }
            float w[N_D], quad = 0.0f;
            for (int i = 0; i < N_D; i++) {
                float v = 0.0f;
                for (int j = 0; j < N_D; j++) v += P[i][j] * mu[j];
                w[i] = v;
                quad += v * mu[i];
            }
            // K'_c = -0.5*(logdet + D*log2pi); K_c = K'_c - 0.5*quad.
            // logit = K_c + (quad form <= 0 shifted) + logpi <= K'_c <= M.
            float kp = -0.5f * (logdet + (float)N_D * LOG2PI);
            float M = kp;
            #pragma unroll
            for (int o = 16; o > 0; o >>= 1)
                M = fmaxf(M, __shfl_xor_sync(0xffffffffu, M, o));
            if (tid == 0) g_M = M;

            float* Wc = (float*)g_W + tid * ROWF;
            int u = 0;
            for (int i = 0; i < N_D; i++)
                for (int j = i; j < N_D; j++)
                    Wc[u++] = (i == j) ? (-0.5f * P[i][i]) : (-P[i][j]);
            Wc[55] = 0.0f;
            for (int i = 0; i < N_D; i++) Wc[56 + i] = w[i];
            Wc[66] = (kp - 0.5f * quad) - M;     // K_c - M
            Wc[67] = 0.0f;
        }

        __shared__ float red[256];
        float acc = 0.0f;
        for (int i = tid; i < N_C; i += 256)
            acc += b_log_sig[i] - 0.5f * b_mu[i] * b_mu[i];
        for (int i = tid; i < N_C * N_T; i += 256)
            acc += beta_log_sig[i] - 0.5f * beta_mu[i] * beta_mu[i];
        red[tid] = acc;
        __syncthreads();
        for (int s2 = 128; s2 > 0; s2 >>= 1) {
            if (tid < s2) red[tid] += red[tid + s2];
            __syncthreads();
        }
        if (tid == 0) g_prior = red[0];
        return;
    }

    // ---- logpi blocks ----
    int warp = (blockIdx.x * blockDim.x + threadIdx.x) >> 5;
    int lane = threadIdx.x & 31;
    if (warp >= N_K * N_T) return;
    int k = warp >> 7;          // N_T = 128
    int t = warp & (N_T - 1);

    float yv  = __ldg(&y[k * N_T + t]);
    float lam = __ldg(&b_mu[lane]) + __ldg(&beta_mu[lane * N_T + t]) * yv;

    float m = lam;
    #pragma unroll
    for (int o = 16; o > 0; o >>= 1)
        m = fmaxf(m, __shfl_xor_sync(0xffffffffu, m, o));
    float e = __expf(lam - m);
    float ssum = e;
    #pragma unroll
    for (int o = 16; o > 0; o >>= 1)
        ssum += __shfl_xor_sync(0xffffffffu, ssum, o);

    g_logpi[warp * N_C + lane] = lam - m - __logf(ssum);
}

// ---------------------------------------------------------------------------
// Kernel 2: main — 2 spikes per thread (W SMEM reads amortized 2x).
// Uniform 34-pair f32x2 dot per component; logpi gathered as float4 per
// 4 components; no-max LSE (logits pre-shifted <= 0 by M).
// ---------------------------------------------------------------------------
__global__ void __launch_bounds__(MAIN_BLOCK)
main_kernel(const float* __restrict__ s,
            const int*   __restrict__ ks,
            const int*   __restrict__ ts,
            float*       __restrict__ out) {
    __shared__ __align__(16) u64 sW[N_C * ROWP];
    __shared__ float sred[MAIN_BLOCK];
    __shared__ unsigned int s_isLast;

    for (int i = threadIdx.x; i < N_C * ROWP; i += MAIN_BLOCK)
        sW[i] = g_W[i];
    __syncthreads();

    int nA = blockIdx.x * MAIN_BLOCK + threadIdx.x;
    float lsum = 0.0f;

    if (nA < N_HALF) {
        int nB = nA + N_HALF;

        // Load both spikes (float2: 8B-aligned rows of 10 floats)
        float svA[N_D], svB[N_D];
        {
            const float2* pA = (const float2*)(s + (size_t)nA * N_D);
            const float2* pB = (const float2*)(s + (size_t)nB * N_D);
            #pragma unroll
            for (int p = 0; p < 5; p++) {
                float2 a = __ldg(&pA[p]); svA[2*p] = a.x; svA[2*p+1] = a.y;
                float2 b = __ldg(&pB[p]); svB[2*p] = b.x; svB[2*p+1] = b.y;
            }
        }

        // Packed feature vectors: 28 quad pairs + 5 linear pairs + (1,0)
        u64 pfA[ROWP], pfB[ROWP];
        {
            float loA = 0.0f, loB = 0.0f;
            int u = 0;
            #pragma unroll
            for (int i = 0; i < N_D; i++) {
                #pragma unroll
                for (int j = i; j < N_D; j++) {
                    float vA = svA[i] * svA[j];
                    float vB = svB[i] * svB[j];
                    if (u & 1) { pfA[u >> 1] = pk2(loA, vA); pfB[u >> 1] = pk2(loB, vB); }
                    else       { loA = vA; loB = vB; }
                    u++;
                }
            }
            pfA[27] = pk2(loA, 0.0f);
            pfB[27] = pk2(loB, 0.0f);
            #pragma unroll
            for (int p = 0; p < 5; p++) {
                pfA[28 + p] = pk2(svA[2*p], svA[2*p+1]);
                pfB[28 + p] = pk2(svB[2*p], svB[2*p+1]);
            }
            pfA[33] = pk2(1.0f, 0.0f);
            pfB[33] = pk2(1.0f, 0.0f);
        }

        const float4* lp4A = (const float4*)(g_logpi +
            ((size_t)(__ldg(&ks[nA]) * N_T + __ldg(&ts[nA]))) * N_C);
        const float4* lp4B = (const float4*)(g_logpi +
            ((size_t)(__ldg(&ks[nB]) * N_T + __ldg(&ts[nB]))) * N_C);

        float ssA = 0.0f, ssB = 0.0f;

        #pragma unroll 1
        for (int g = 0; g < 8; g++) {
            float4 lA = __ldg(&lp4A[g]);
            float4 lB = __ldg(&lp4B[g]);
            const float* lAf = (const float*)&lA;
            const float* lBf = (const float*)&lB;

            #pragma unroll
            for (int cc = 0; cc < 4; cc++) {
                const ulonglong2* w2 =
                    reinterpret_cast<const ulonglong2*>(sW + (g * 4 + cc) * ROWP);
                u64 aA0 = 0ull, aA1 = 0ull, aA2 = 0ull, aA3 = 0ull;
                u64 aB0 = 0ull, aB1 = 0ull, aB2 = 0ull, aB3 = 0ull;
                #pragma unroll
                for (int p = 0; p < 17; p++) {
                    ulonglong2 w = w2[p];
                    if (p & 1) {
                        fma2(aA2, w.x, pfA[2*p]); fma2(aA3, w.y, pfA[2*p+1]);
                        fma2(aB2, w.x, pfB[2*p]); fma2(aB3, w.y, pfB[2*p+1]);
                    } else {
                        fma2(aA0, w.x, pfA[2*p]); fma2(aA1, w.y, pfA[2*p+1]);
                        fma2(aB0, w.x, pfB[2*p]); fma2(aB1, w.y, pfB[2*p+1]);
                    }
                }
                float2 qA = upk(add2(add2(aA0, aA1), add2(aA2, aA3)));
                float2 qB = upk(add2(add2(aB0, aB1), add2(aB2, aB3)));
                float logitA = (qA.x + qA.y) + lAf[cc];   // <= 0
                float logitB = (qB.x + qB.y) + lBf[cc];   // <= 0
                ssA += __expf(logitA);
                ssB += __expf(logitB);
            }
        }
        lsum = __logf(fmaxf(ssA, 1e-30f)) + __logf(fmaxf(ssB, 1e-30f));
    }

    sred[threadIdx.x] = lsum;
    __syncthreads();
    #pragma unroll
    for (int s2 = MAIN_BLOCK / 2; s2 > 0; s2 >>= 1) {
        if (threadIdx.x < s2) sred[threadIdx.x] += sred[threadIdx.x + s2];
        __syncthreads();
    }
    if (threadIdx.x == 0) {
        g_partial[blockIdx.x] = sred[0];
        __threadfence();
        unsigned int prev = atomicAdd(&g_count, 1u);
        s_isLast = (prev == (unsigned int)(NBLOCKS - 1)) ? 1u : 0u;
    }
    __syncthreads();

    if (s_isLast) {
        // Deterministic final reduce: fixed-order strided double sums + fixed tree.
        __shared__ double dred[MAIN_BLOCK];
        const volatile float* vp = g_partial;
        double acc = 0.0;
        for (int i = threadIdx.x; i < NBLOCKS; i += MAIN_BLOCK)
            acc += (double)vp[i];
        dred[threadIdx.x] = acc;
        __syncthreads();
        for (int s2 = MAIN_BLOCK / 2; s2 > 0; s2 >>= 1) {
            if (threadIdx.x < s2) dred[threadIdx.x] += dred[threadIdx.x + s2];
            __syncthreads();
        }
        if (threadIdx.x == 0)
            out[0] = (float)(dred[0] + (double)g_prior
                             + (double)N_SPK * (double)g_M);
    }
}

// ---------------------------------------------------------------------------
extern "C" void kernel_launch(void* const* d_in, const int* in_sizes, int n_in,
                              void* d_out, int out_size) {
    const float* s            = (const float*)d_in[0];
    const float* y            = (const float*)d_in[1];
    const int*   ks           = (const int*)  d_in[2];
    const int*   ts           = (const int*)  d_in[3];
    const float* means        = (const float*)d_in[4];
    const float* covs         = (const float*)d_in[5];
    const float* b_mu         = (const float*)d_in[6];
    const float* b_log_sig    = (const float*)d_in[7];
    const float* beta_mu      = (const float*)d_in[8];
    const float* beta_log_sig = (const float*)d_in[9];

    // logpi: 32768 (k,t) warps -> 4096 blocks of 256; +1 setup block
    logpi_setup_kernel<<<(N_K * N_T * 32) / 256 + 1, 256>>>(
        y, b_mu, beta_mu, means, covs, b_log_sig, beta_log_sig);

    main_kernel<<<NBLOCKS, MAIN_BLOCK>>>(s, ks, ts, (float*)d_out);
}

// round 13
// speedup vs baseline: 1.5623x; 1.2055x over previous
#include <cuda_runtime.h>
#include <math.h>

#define N_K   256
#define N_T   128
#define N_C   32
#define N_D   10
#define N_SPK 1000000
#define LOG2PI 1.8378770664093453f

// Packed coefficient row per component: 34 f32-pairs (68 floats, 272B):
// pairs [0..27]  : quad coeffs over upper-tri features s_i*s_j (i<=j), pad 0 in slot 55
// pairs [28..32] : linear coeffs (P @ mu)
// pair  [33]     : (K_c - M, 0)  -- consumed as a scalar constant
#define ROWF 68
#define ROWP 34
#define NPAIR 33           // feature pairs actually held in registers

#define MAIN_BLOCK 128
#define N_HALF (N_SPK / 2)                       // 500000 threads, 2 spikes each
#define NBLOCKS ((N_HALF + MAIN_BLOCK - 1) / MAIN_BLOCK)

typedef unsigned long long u64;

__device__ __align__(16) u64 g_W[N_C * ROWP];
__device__ float g_prior;
__device__ float g_M;                            // global logit upper bound
__device__ float g_logpi[N_K * N_T * N_C];       // (k,t,c)-major, 4 MB, L2-resident
__device__ float g_partial[NBLOCKS];
__device__ unsigned int g_count;

// ---- f32x2 packed-math helpers (Blackwell dual-fp32 pipe, PTX-only) ----
__device__ __forceinline__ u64 pk2(float lo, float hi) {
    u64 r; asm("mov.b64 %0,{%1,%2};" : "=l"(r) : "f"(lo), "f"(hi)); return r;
}
__device__ __forceinline__ void fma2(u64& d, u64 a, u64 b) {
    asm("fma.rn.f32x2 %0,%1,%2,%3;" : "=l"(d) : "l"(a), "l"(b), "l"(d));
}
__device__ __forceinline__ u64 add2(u64 a, u64 b) {
    u64 r; asm("add.rn.f32x2 %0,%1,%2;" : "=l"(r) : "l"(a), "l"(b)); return r;
}
__device__ __forceinline__ float2 upk(u64 a) {
    float2 v; asm("mov.b64 {%0,%1},%2;" : "=f"(v.x), "=f"(v.y) : "l"(a)); return v;
}

// ---------------------------------------------------------------------------
// Kernel 1: log_pi table (warp per (k,t), lane = component), PLUS one extra
// block (blockIdx == gridDim-1): Cholesky -> packed coefficients with the
// global bound M folded in, prior term, g_count reset.
// ---------------------------------------------------------------------------
__global__ void logpi_setup_kernel(const float* __restrict__ y,
                                   const float* __restrict__ b_mu,
                                   const float* __restrict__ beta_mu,
                                   const float* __restrict__ means,
                                   const float* __restrict__ covs,
                                   const float* __restrict__ b_log_sig,
                                   const float* __restrict__ beta_log_sig) {
    if (blockIdx.x == gridDim.x - 1) {
        int tid = threadIdx.x;
        if (tid == 0) g_count = 0;

        if (tid < N_C) {
            const float* cov = covs + tid * N_D * N_D;
            const float* mu  = means + tid * N_D;

            float L[N_D][N_D];
            float logdet = 0.0f;
            for (int j = 0; j < N_D; j++) {
                float sdiag = cov[j * N_D + j];
                for (int k = 0; k < j; k++) sdiag -= L[j][k] * L[j][k];
                float d = sqrtf(sdiag);
                L[j][j] = d;
                logdet += 2.0f * logf(d);
                for (int i = j + 1; i < N_D; i++) {
                    float v = cov[i * N_D + j];
                    for (int k = 0; k < j; k++) v -= L[i][k] * L[j][k];
                    L[i][j] = v / d;
                }
            }
            float Li[N_D][N_D];
            for (int j = 0; j < N_D; j++)
                for (int i = 0; i < N_D; i++) {
                    if (i < j) { Li[i][j] = 0.0f; continue; }
                    float v = (i == j) ? 1.0f : 0.0f;
                    for (int k = j; k < i; k++) v -= L[i][k] * Li[k][j];
                    Li[i][j] = v / L[i][i];
                }
            float P[N_D][N_D];
            for (int i = 0; i < N_D; i++)
                for (int j = 0; j < N_D; j++) {
                    float v = 0.0f;
                    int k0 = (i > j) ? i : j;
                    for (int k = k0; k < N_D; k++) v += Li[k][i] * Li[k][j];
                    P[i][j] = v;
                }
            float w[N_D], quad = 0.0f;
            for (int i = 0; i < N_D; i++) {
                float v = 0.0f;
                for (int j = 0; j < N_D; j++) v += P[i][j] * mu[j];
                w[i] = v;
                quad += v * mu[i];
            }
            // K'_c = -0.5*(logdet + D*log2pi); K_c = K'_c - 0.5*quad.
            // logit = K_c + (quad form <= 0) + linear-shift + logpi <= K'_c <= M.
            float kp = -0.5f * (logdet + (float)N_D * LOG2PI);
            float M = kp;
            #pragma unroll
            for (int o = 16; o > 0; o >>= 1)
                M = fmaxf(M, __shfl_xor_sync(0xffffffffu, M, o));
            if (tid == 0) g_M = M;

            float* Wc = (float*)g_W + tid * ROWF;
            int u = 0;
            for (int i = 0; i < N_D; i++)
                for (int j = i; j < N_D; j++)
                    Wc[u++] = (i == j) ? (-0.5f * P[i][i]) : (-P[i][j]);
            Wc[55] = 0.0f;
            for (int i = 0; i < N_D; i++) Wc[56 + i] = w[i];
            Wc[66] = (kp - 0.5f * quad) - M;     // K_c - M
            Wc[67] = 0.0f;
        }

        __shared__ float red[256];
        float acc = 0.0f;
        for (int i = tid; i < N_C; i += 256)
            acc += b_log_sig[i] - 0.5f * b_mu[i] * b_mu[i];
        for (int i = tid; i < N_C * N_T; i += 256)
            acc += beta_log_sig[i] - 0.5f * beta_mu[i] * beta_mu[i];
        red[tid] = acc;
        __syncthreads();
        for (int s2 = 128; s2 > 0; s2 >>= 1) {
            if (tid < s2) red[tid] += red[tid + s2];
            __syncthreads();
        }
        if (tid == 0) g_prior = red[0];
        return;
    }

    // ---- logpi blocks ----
    int warp = (blockIdx.x * blockDim.x + threadIdx.x) >> 5;
    int lane = threadIdx.x & 31;
    if (warp >= N_K * N_T) return;
    int k = warp >> 7;          // N_T = 128
    int t = warp & (N_T - 1);

    float yv  = __ldg(&y[k * N_T + t]);
    float lam = __ldg(&b_mu[lane]) + __ldg(&beta_mu[lane * N_T + t]) * yv;

    float m = lam;
    #pragma unroll
    for (int o = 16; o > 0; o >>= 1)
        m = fmaxf(m, __shfl_xor_sync(0xffffffffu, m, o));
    float e = __expf(lam - m);
    float ssum = e;
    #pragma unroll
    for (int o = 16; o > 0; o >>= 1)
        ssum += __shfl_xor_sync(0xffffffffu, ssum, o);

    g_logpi[warp * N_C + lane] = lam - m - __logf(ssum);
}

// ---------------------------------------------------------------------------
// Kernel 2: main — 2 spikes per thread. 33 feature pairs per spike in regs;
// per component: 17 x LDS.128 + 33x2 fma.rn.f32x2 over 4 accumulators,
// scalar K_c-M add, no-max LSE. __launch_bounds__(128,3): <=168 regs so
// 3 CTAs/SM (12 warps) — occupancy was the R7 limiter (occ 12.4%, issue 27%).
// ---------------------------------------------------------------------------
__global__ void __launch_bounds__(MAIN_BLOCK, 3)
main_kernel(const float* __restrict__ s,
            const int*   __restrict__ ks,
            const int*   __restrict__ ts,
            float*       __restrict__ out) {
    __shared__ __align__(16) u64 sW[N_C * ROWP];
    __shared__ float sred[MAIN_BLOCK];
    __shared__ unsigned int s_isLast;

    for (int i = threadIdx.x; i < N_C * ROWP; i += MAIN_BLOCK)
        sW[i] = g_W[i];
    __syncthreads();

    int nA = blockIdx.x * MAIN_BLOCK + threadIdx.x;
    float lsum = 0.0f;

    if (nA < N_HALF) {
        int nB = nA + N_HALF;

        // Load both spikes (float2: 8B-aligned rows of 10 floats)
        float svA[N_D], svB[N_D];
        {
            const float2* pA = (const float2*)(s + (size_t)nA * N_D);
            const float2* pB = (const float2*)(s + (size_t)nB * N_D);
            #pragma unroll
            for (int p = 0; p < 5; p++) {
                float2 a = __ldg(&pA[p]); svA[2*p] = a.x; svA[2*p+1] = a.y;
                float2 b = __ldg(&pB[p]); svB[2*p] = b.x; svB[2*p+1] = b.y;
            }
        }

        // Packed feature vectors: 28 quad pairs + 5 linear pairs = 33 pairs
        u64 pfA[NPAIR], pfB[NPAIR];
        {
            float loA = 0.0f, loB = 0.0f;
            int u = 0;
            #pragma unroll
            for (int i = 0; i < N_D; i++) {
                #pragma unroll
                for (int j = i; j < N_D; j++) {
                    float vA = svA[i] * svA[j];
                    float vB = svB[i] * svB[j];
                    if (u & 1) { pfA[u >> 1] = pk2(loA, vA); pfB[u >> 1] = pk2(loB, vB); }
                    else       { loA = vA; loB = vB; }
                    u++;
                }
            }
            pfA[27] = pk2(loA, 0.0f);
            pfB[27] = pk2(loB, 0.0f);
            #pragma unroll
            for (int p = 0; p < 5; p++) {
                pfA[28 + p] = pk2(svA[2*p], svA[2*p+1]);
                pfB[28 + p] = pk2(svB[2*p], svB[2*p+1]);
            }
        }

        const float4* lp4A = (const float4*)(g_logpi +
            ((size_t)(__ldg(&ks[nA]) * N_T + __ldg(&ts[nA]))) * N_C);
        const float4* lp4B = (const float4*)(g_logpi +
            ((size_t)(__ldg(&ks[nB]) * N_T + __ldg(&ts[nB]))) * N_C);

        float ssA = 0.0f, ssB = 0.0f;

        #pragma unroll 1
        for (int g = 0; g < 8; g++) {
            float4 lA = __ldg(&lp4A[g]);
            float4 lB = __ldg(&lp4B[g]);
            const float* lAf = (const float*)&lA;
            const float* lBf = (const float*)&lB;

            #pragma unroll
            for (int cc = 0; cc < 4; cc++) {
                const ulonglong2* w2 =
                    reinterpret_cast<const ulonglong2*>(sW + (g * 4 + cc) * ROWP);
                u64 aA0 = 0ull, aA1 = 0ull;
                u64 aB0 = 0ull, aB1 = 0ull;
                #pragma unroll
                for (int p = 0; p < 16; p++) {
                    ulonglong2 w = w2[p];
                    fma2(aA0, w.x, pfA[2*p]); fma2(aA1, w.y, pfA[2*p+1]);
                    fma2(aB0, w.x, pfB[2*p]); fma2(aB1, w.y, pfB[2*p+1]);
                }
                ulonglong2 wl = w2[16];                 // pair 32 (linear) + pair 33 (const)
                fma2(aA0, wl.x, pfA[32]);
                fma2(aB0, wl.x, pfB[32]);
                float kc = upk(wl.y).x;                 // K_c - M

                float2 qA = upk(add2(aA0, aA1));
                float2 qB = upk(add2(aB0, aB1));
                float logitA = (qA.x + qA.y) + kc + lAf[cc];   // <= 0
                float logitB = (qB.x + qB.y) + kc + lBf[cc];   // <= 0
                ssA += __expf(logitA);
                ssB += __expf(logitB);
            }
        }
        lsum = __logf(fmaxf(ssA, 1e-30f)) + __logf(fmaxf(ssB, 1e-30f));
    }

    sred[threadIdx.x] = lsum;
    __syncthreads();
    #pragma unroll
    for (int s2 = MAIN_BLOCK / 2; s2 > 0; s2 >>= 1) {
        if (threadIdx.x < s2) sred[threadIdx.x] += sred[threadIdx.x + s2];
        __syncthreads();
    }
    if (threadIdx.x == 0) {
        g_partial[blockIdx.x] = sred[0];
        __threadfence();
        unsigned int prev = atomicAdd(&g_count, 1u);
        s_isLast = (prev == (unsigned int)(NBLOCKS - 1)) ? 1u : 0u;
    }
    __syncthreads();

    if (s_isLast) {
        // Deterministic final reduce: fixed-order strided double sums + fixed tree.
        __shared__ double dred[MAIN_BLOCK];
        const volatile float* vp = g_partial;
        double acc = 0.0;
        for (int i = threadIdx.x; i < NBLOCKS; i += MAIN_BLOCK)
            acc += (double)vp[i];
        dred[threadIdx.x] = acc;
        __syncthreads();
        for (int s2 = MAIN_BLOCK / 2; s2 > 0; s2 >>= 1) {
            if (threadIdx.x < s2) dred[threadIdx.x] += dred[threadIdx.x + s2];
            __syncthreads();
        }
        if (threadIdx.x == 0)
            out[0] = (float)(dred[0] + (double)g_prior
                             + (double)N_SPK * (double)g_M);
    }
}

// ---------------------------------------------------------------------------
extern "C" void kernel_launch(void* const* d_in, const int* in_sizes, int n_in,
                              void* d_out, int out_size) {
    const float* s            = (const float*)d_in[0];
    const float* y            = (const float*)d_in[1];
    const int*   ks           = (const int*)  d_in[2];
    const int*   ts           = (const int*)  d_in[3];
    const float* means        = (const float*)d_in[4];
    const float* covs         = (const float*)d_in[5];
    const float* b_mu         = (const float*)d_in[6];
    const float* b_log_sig    = (const float*)d_in[7];
    const float* beta_mu      = (const float*)d_in[8];
    const float* beta_log_sig = (const float*)d_in[9];

    // logpi: 32768 (k,t) warps -> 4096 blocks of 256; +1 setup block
    logpi_setup_kernel<<<(N_K * N_T * 32) / 256 + 1, 256>>>(
        y, b_mu, beta_mu, means, covs, b_log_sig, beta_log_sig);

    main_kernel<<<NBLOCKS, MAIN_BLOCK>>>(s, ks, ts, (float*)d_out);
}

// round 14
// speedup vs baseline: 1.9060x; 1.2200x over previous
#include <cuda_runtime.h>
#include <math.h>

#define N_K   256
#define N_T   128
#define N_C   32
#define N_D   10
#define N_SPK 1000000
#define LOG2PI 1.8378770664093453f

// Packed coefficient row per component: 34 f32-pairs (68 floats, 272B):
// pairs [0..27]  : quad coeffs over upper-tri features s_i*s_j (i<=j), pad 0 in slot 55
// pairs [28..32] : linear coeffs (P @ mu)
// pair  [33]     : (K_c - M, 0)  -- consumed as a scalar constant
#define ROWF 68
#define ROWP 34
#define ROWQ 17            // ulonglong2 (16B) quads per row
#define NPAIR 33           // feature pairs held in registers
#define NCONSTQ 10         // W quads read from constant bank (rest from SMEM)

#define MAIN_BLOCK 128
#define N_HALF (N_SPK / 2)                       // 500000 threads, 2 spikes each
#define NBLOCKS ((N_HALF + MAIN_BLOCK - 1) / MAIN_BLOCK)

typedef unsigned long long u64;

__device__ __align__(16) u64 g_W[N_C * ROWP];
__constant__ __align__(16) u64 c_W[N_C * ROWP];  // copy of g_W, const-port operands
__device__ float g_prior;
__device__ float g_M;                            // global logit upper bound
__device__ float g_logpi[N_K * N_T * N_C];       // (k,t,c)-major, 4 MB, L2-resident
__device__ float g_partial[NBLOCKS];
__device__ unsigned int g_count;

// ---- f32x2 packed-math helpers (Blackwell dual-fp32 pipe, PTX-only) ----
__device__ __forceinline__ u64 pk2(float lo, float hi) {
    u64 r; asm("mov.b64 %0,{%1,%2};" : "=l"(r) : "f"(lo), "f"(hi)); return r;
}
__device__ __forceinline__ void fma2(u64& d, u64 a, u64 b) {
    asm("fma.rn.f32x2 %0,%1,%2,%3;" : "=l"(d) : "l"(a), "l"(b), "l"(d));
}
__device__ __forceinline__ u64 add2(u64 a, u64 b) {
    u64 r; asm("add.rn.f32x2 %0,%1,%2;" : "=l"(r) : "l"(a), "l"(b)); return r;
}
__device__ __forceinline__ float2 upk(u64 a) {
    float2 v; asm("mov.b64 {%0,%1},%2;" : "=f"(v.x), "=f"(v.y) : "l"(a)); return v;
}

// ---------------------------------------------------------------------------
// Kernel 1: log_pi table (warp per (k,t), lane = component), PLUS one extra
// block (blockIdx == gridDim-1): Cholesky -> packed coefficients with the
// global bound M folded in, prior term, g_count reset.
// ---------------------------------------------------------------------------
__global__ void logpi_setup_kernel(const float* __restrict__ y,
                                   const float* __restrict__ b_mu,
                                   const float* __restrict__ beta_mu,
                                   const float* __restrict__ means,
                                   const float* __restrict__ covs,
                                   const float* __restrict__ b_log_sig,
                                   const float* __restrict__ beta_log_sig) {
    if (blockIdx.x == gridDim.x - 1) {
        int tid = threadIdx.x;
        if (tid == 0) g_count = 0;

        if (tid < N_C) {
            const float* cov = covs + tid * N_D * N_D;
            const float* mu  = means + tid * N_D;

            float L[N_D][N_D];
            float logdet = 0.0f;
            for (int j = 0; j < N_D; j++) {
                float sdiag = cov[j * N_D + j];
                for (int k = 0; k < j; k++) sdiag -= L[j][k] * L[j][k];
                float d = sqrtf(sdiag);
                L[j][j] = d;
                logdet += 2.0f * logf(d);
                for (int i = j + 1; i < N_D; i++) {
                    float v = cov[i * N_D + j];
                    for (int k = 0; k < j; k++) v -= L[i][k] * L[j][k];
                    L[i][j] = v / d;
                }
            }
            float Li[N_D][N_D];
            for (int j = 0; j < N_D; j++)
                for (int i = 0; i < N_D; i++) {
                    if (i < j) { Li[i][j] = 0.0f; continue; }
                    float v = (i == j) ? 1.0f : 0.0f;
                    for (int k = j; k < i; k++) v -= L[i][k] * Li[k][j];
                    Li[i][j] = v / L[i][i];
                }
            float P[N_D][N_D];
            for (int i = 0; i < N_D; i++)
                for (int j = 0; j < N_D; j++) {
                    float v = 0.0f;
                    int k0 = (i > j) ? i : j;
                    for (int k = k0; k < N_D; k++) v += Li[k][i] * Li[k][j];
                    P[i][j] = v;
                }
            float w[N_D], quad = 0.0f;
            for (int i = 0; i < N_D; i++) {
                float v = 0.0f;
                for (int j = 0; j < N_D; j++) v += P[i][j] * mu[j];
                w[i] = v;
                quad += v * mu[i];
            }
            // K'_c = -0.5*(logdet + D*log2pi); K_c = K'_c - 0.5*quad.
            // logit = K_c + (quad form <= 0) + linear-shift + logpi <= K'_c <= M.
            float kp = -0.5f * (logdet + (float)N_D * LOG2PI);
            float M = kp;
            #pragma unroll
            for (int o = 16; o > 0; o >>= 1)
                M = fmaxf(M, __shfl_xor_sync(0xffffffffu, M, o));
            if (tid == 0) g_M = M;

            float* Wc = (float*)g_W + tid * ROWF;
            int u = 0;
            for (int i = 0; i < N_D; i++)
                for (int j = i; j < N_D; j++)
                    Wc[u++] = (i == j) ? (-0.5f * P[i][i]) : (-P[i][j]);
            Wc[55] = 0.0f;
            for (int i = 0; i < N_D; i++) Wc[56 + i] = w[i];
            Wc[66] = (kp - 0.5f * quad) - M;     // K_c - M
            Wc[67] = 0.0f;
        }

        __shared__ float red[256];
        float acc = 0.0f;
        for (int i = tid; i < N_C; i += 256)
            acc += b_log_sig[i] - 0.5f * b_mu[i] * b_mu[i];
        for (int i = tid; i < N_C * N_T; i += 256)
            acc += beta_log_sig[i] - 0.5f * beta_mu[i] * beta_mu[i];
        red[tid] = acc;
        __syncthreads();
        for (int s2 = 128; s2 > 0; s2 >>= 1) {
            if (tid < s2) red[tid] += red[tid + s2];
            __syncthreads();
        }
        if (tid == 0) g_prior = red[0];
        return;
    }

    // ---- logpi blocks ----
    int warp = (blockIdx.x * blockDim.x + threadIdx.x) >> 5;
    int lane = threadIdx.x & 31;
    if (warp >= N_K * N_T) return;
    int k = warp >> 7;          // N_T = 128
    int t = warp & (N_T - 1);

    float yv  = __ldg(&y[k * N_T + t]);
    float lam = __ldg(&b_mu[lane]) + __ldg(&beta_mu[lane * N_T + t]) * yv;

    float m = lam;
    #pragma unroll
    for (int o = 16; o > 0; o >>= 1)
        m = fmaxf(m, __shfl_xor_sync(0xffffffffu, m, o));
    float e = __expf(lam - m);
    float ssum = e;
    #pragma unroll
    for (int o = 16; o > 0; o >>= 1)
        ssum += __shfl_xor_sync(0xffffffffu, ssum, o);

    g_logpi[warp * N_C + lane] = lam - m - __logf(ssum);
}

// ---------------------------------------------------------------------------
// Kernel 2: main — 2 spikes per thread, 33 feature pairs/spike in regs.
// Per component: W quads 0..9 from the CONSTANT bank (idle const port,
// warp-uniform index -> broadcast LDC.128), quads 10..16 from SMEM
// (balances const port vs L1 crossbar, which was 60% busy in R10).
// Scalar K_c-M add, no-max LSE. __launch_bounds__(128,3): 3 CTAs/SM.
// ---------------------------------------------------------------------------
__global__ void __launch_bounds__(MAIN_BLOCK, 3)
main_kernel(const float* __restrict__ s,
            const int*   __restrict__ ks,
            const int*   __restrict__ ts,
            float*       __restrict__ out) {
    __shared__ __align__(16) u64 sW[N_C * ROWP];
    __shared__ float sred[MAIN_BLOCK];
    __shared__ unsigned int s_isLast;

    for (int i = threadIdx.x; i < N_C * ROWP; i += MAIN_BLOCK)
        sW[i] = g_W[i];
    __syncthreads();

    int nA = blockIdx.x * MAIN_BLOCK + threadIdx.x;
    float lsum = 0.0f;

    if (nA < N_HALF) {
        int nB = nA + N_HALF;

        // Load both spikes (float2: 8B-aligned rows of 10 floats)
        float svA[N_D], svB[N_D];
        {
            const float2* pA = (const float2*)(s + (size_t)nA * N_D);
            const float2* pB = (const float2*)(s + (size_t)nB * N_D);
            #pragma unroll
            for (int p = 0; p < 5; p++) {
                float2 a = __ldg(&pA[p]); svA[2*p] = a.x; svA[2*p+1] = a.y;
                float2 b = __ldg(&pB[p]); svB[2*p] = b.x; svB[2*p+1] = b.y;
            }
        }

        // Packed feature vectors: 28 quad pairs + 5 linear pairs = 33 pairs
        u64 pfA[NPAIR], pfB[NPAIR];
        {
            float loA = 0.0f, loB = 0.0f;
            int u = 0;
            #pragma unroll
            for (int i = 0; i < N_D; i++) {
                #pragma unroll
                for (int j = i; j < N_D; j++) {
                    float vA = svA[i] * svA[j];
                    float vB = svB[i] * svB[j];
                    if (u & 1) { pfA[u >> 1] = pk2(loA, vA); pfB[u >> 1] = pk2(loB, vB); }
                    else       { loA = vA; loB = vB; }
                    u++;
                }
            }
            pfA[27] = pk2(loA, 0.0f);
            pfB[27] = pk2(loB, 0.0f);
            #pragma unroll
            for (int p = 0; p < 5; p++) {
                pfA[28 + p] = pk2(svA[2*p], svA[2*p+1]);
                pfB[28 + p] = pk2(svB[2*p], svB[2*p+1]);
            }
        }

        const float4* lp4A = (const float4*)(g_logpi +
            ((size_t)(__ldg(&ks[nA]) * N_T + __ldg(&ts[nA]))) * N_C);
        const float4* lp4B = (const float4*)(g_logpi +
            ((size_t)(__ldg(&ks[nB]) * N_T + __ldg(&ts[nB]))) * N_C);

        const ulonglong2* cw2 = reinterpret_cast<const ulonglong2*>(c_W);

        float ssA = 0.0f, ssB = 0.0f;

        #pragma unroll 1
        for (int g = 0; g < 8; g++) {
            float4 lA = __ldg(&lp4A[g]);
            float4 lB = __ldg(&lp4B[g]);
            const float* lAf = (const float*)&lA;
            const float* lBf = (const float*)&lB;

            #pragma unroll
            for (int cc = 0; cc < 4; cc++) {
                int c = g * 4 + cc;
                const ulonglong2* w2 =
                    reinterpret_cast<const ulonglong2*>(sW + c * ROWP);
                u64 aA0 = 0ull, aA1 = 0ull;
                u64 aB0 = 0ull, aB1 = 0ull;
                // Quads 0..NCONSTQ-1 from the constant bank (LDC.128 broadcast)
                #pragma unroll
                for (int p = 0; p < NCONSTQ; p++) {
                    ulonglong2 w = cw2[c * ROWQ + p];
                    fma2(aA0, w.x, pfA[2*p]); fma2(aA1, w.y, pfA[2*p+1]);
                    fma2(aB0, w.x, pfB[2*p]); fma2(aB1, w.y, pfB[2*p+1]);
                }
                // Quads NCONSTQ..15 from SMEM (LDS.128 broadcast)
                #pragma unroll
                for (int p = NCONSTQ; p < 16; p++) {
                    ulonglong2 w = w2[p];
                    fma2(aA0, w.x, pfA[2*p]); fma2(aA1, w.y, pfA[2*p+1]);
                    fma2(aB0, w.x, pfB[2*p]); fma2(aB1, w.y, pfB[2*p+1]);
                }
                ulonglong2 wl = w2[16];                 // pair 32 (linear) + pair 33 (const)
                fma2(aA0, wl.x, pfA[32]);
                fma2(aB0, wl.x, pfB[32]);
                float kc = upk(wl.y).x;                 // K_c - M

                float2 qA = upk(add2(aA0, aA1));
                float2 qB = upk(add2(aB0, aB1));
                float logitA = (qA.x + qA.y) + kc + lAf[cc];   // <= 0
                float logitB = (qB.x + qB.y) + kc + lBf[cc];   // <= 0
                ssA += __expf(logitA);
                ssB += __expf(logitB);
            }
        }
        lsum = __logf(fmaxf(ssA, 1e-30f)) + __logf(fmaxf(ssB, 1e-30f));
    }

    sred[threadIdx.x] = lsum;
    __syncthreads();
    #pragma unroll
    for (int s2 = MAIN_BLOCK / 2; s2 > 0; s2 >>= 1) {
        if (threadIdx.x < s2) sred[threadIdx.x] += sred[threadIdx.x + s2];
        __syncthreads();
    }
    if (threadIdx.x == 0) {
        g_partial[blockIdx.x] = sred[0];
        __threadfence();
        unsigned int prev = atomicAdd(&g_count, 1u);
        s_isLast = (prev == (unsigned int)(NBLOCKS - 1)) ? 1u : 0u;
    }
    __syncthreads();

    if (s_isLast) {
        // Deterministic final reduce: fixed-order strided double sums + fixed tree.
        __shared__ double dred[MAIN_BLOCK];
        const volatile float* vp = g_partial;
        double acc = 0.0;
        for (int i = threadIdx.x; i < NBLOCKS; i += MAIN_BLOCK)
            acc += (double)vp[i];
        dred[threadIdx.x] = acc;
        __syncthreads();
        for (int s2 = MAIN_BLOCK / 2; s2 > 0; s2 >>= 1) {
            if (threadIdx.x < s2) dred[threadIdx.x] += dred[threadIdx.x + s2];
            __syncthreads();
        }
        if (threadIdx.x == 0)
            out[0] = (float)(dred[0] + (double)g_prior
                             + (double)N_SPK * (double)g_M);
    }
}

// ---------------------------------------------------------------------------
extern "C" void kernel_launch(void* const* d_in, const int* in_sizes, int n_in,
                              void* d_out, int out_size) {
    const float* s            = (const float*)d_in[0];
    const float* y            = (const float*)d_in[1];
    const int*   ks           = (const int*)  d_in[2];
    const int*   ts           = (const int*)  d_in[3];
    const float* means        = (const float*)d_in[4];
    const float* covs         = (const float*)d_in[5];
    const float* b_mu         = (const float*)d_in[6];
    const float* b_log_sig    = (const float*)d_in[7];
    const float* beta_mu      = (const float*)d_in[8];
    const float* beta_log_sig = (const float*)d_in[9];

    // logpi: 32768 (k,t) warps -> 4096 blocks of 256; +1 setup block
    logpi_setup_kernel<<<(N_K * N_T * 32) / 256 + 1, 256>>>(
        y, b_mu, beta_mu, means, covs, b_log_sig, beta_log_sig);

    // Mirror the device-computed W into the constant bank (D2D memcpy node,
    // graph-capturable; no allocation).
    void* g_W_addr = nullptr;
    cudaGetSymbolAddress(&g_W_addr, g_W);
    cudaMemcpyToSymbolAsync(c_W, g_W_addr, sizeof(u64) * N_C * ROWP, 0,
                            cudaMemcpyDeviceToDevice);

    main_kernel<<<NBLOCKS, MAIN_BLOCK>>>(s, ks, ts, (float*)d_out);
}

// round 16
// speedup vs baseline: 1.9555x; 1.0260x over previous
#include <cuda_runtime.h>
#include <math.h>

#define N_K   256
#define N_T   128
#define N_C   32
#define N_D   10
#define N_SPK 1000000
#define LOG2PI 1.8378770664093453f

// NESTED coefficient row per component (68 floats = 34 pairs = 17 quads):
// pairs  0..24 : t-stage j-pairs, rows i=0..8 in order; even rows start j=i
//                (diag included), odd rows start j=i+1 (diag split out)
// pairs 25..27 : odd/last diagonals vs squares: (-P11/2,-P33/2),(-P55/2,-P77/2),(-P99/2,0)
// pairs 28..32 : linear coeffs (P @ mu) vs s-pairs
// pair  33     : (K_c - M, 0)
#define ROWF 68
#define ROWP 34
#define ROWQ 17
#define NCONSTQ 10         // quads 0..9 from constant bank, 10..16 from SMEM

#define MAIN_BLOCK 128
#define N_HALF (N_SPK / 2)                       // 500000 threads, 2 spikes each
#define NBLOCKS ((N_HALF + MAIN_BLOCK - 1) / MAIN_BLOCK)

typedef unsigned long long u64;

__device__ __align__(16) u64 g_W[N_C * ROWP];
__constant__ __align__(16) u64 c_W[N_C * ROWP];
__device__ float g_prior;
__device__ float g_M;
__device__ float g_logpi[N_K * N_T * N_C];       // (k,t,c)-major, 4 MB, L2-resident
__device__ float g_partial[NBLOCKS];
__device__ unsigned int g_count;

// ---- f32x2 packed-math helpers (Blackwell dual-fp32 pipe, PTX-only) ----
__device__ __forceinline__ u64 pk2(float lo, float hi) {
    u64 r; asm("mov.b64 %0,{%1,%2};" : "=l"(r) : "f"(lo), "f"(hi)); return r;
}
__device__ __forceinline__ void fma2(u64& d, u64 a, u64 b) {
    asm("fma.rn.f32x2 %0,%1,%2,%3;" : "=l"(d) : "l"(a), "l"(b), "l"(d));
}
__device__ __forceinline__ u64 mul2(u64 a, u64 b) {
    u64 r; asm("mul.rn.f32x2 %0,%1,%2;" : "=l"(r) : "l"(a), "l"(b)); return r;
}
__device__ __forceinline__ u64 add2(u64 a, u64 b) {
    u64 r; asm("add.rn.f32x2 %0,%1,%2;" : "=l"(r) : "l"(a), "l"(b)); return r;
}
__device__ __forceinline__ float2 upk(u64 a) {
    float2 v; asm("mov.b64 {%0,%1},%2;" : "=f"(v.x), "=f"(v.y) : "l"(a)); return v;
}

// ---------------------------------------------------------------------------
// Kernel 1: log_pi table (warp per (k,t), lane = component) + one setup block.
// ---------------------------------------------------------------------------
__global__ void logpi_setup_kernel(const float* __restrict__ y,
                                   const float* __restrict__ b_mu,
                                   const float* __restrict__ beta_mu,
                                   const float* __restrict__ means,
                                   const float* __restrict__ covs,
                                   const float* __restrict__ b_log_sig,
                                   const float* __restrict__ beta_log_sig) {
    if (blockIdx.x == gridDim.x - 1) {
        int tid = threadIdx.x;
        if (tid == 0) g_count = 0;

        if (tid < N_C) {
            const float* cov = covs + tid * N_D * N_D;
            const float* mu  = means + tid * N_D;

            float L[N_D][N_D];
            float logdet = 0.0f;
            for (int j = 0; j < N_D; j++) {
                float sdiag = cov[j * N_D + j];
                for (int k = 0; k < j; k++) sdiag -= L[j][k] * L[j][k];
                float d = sqrtf(sdiag);
                L[j][j] = d;
                logdet += 2.0f * logf(d);
                for (int i = j + 1; i < N_D; i++) {
                    float v = cov[i * N_D + j];
                    for (int k = 0; k < j; k++) v -= L[i][k] * L[j][k];
                    L[i][j] = v / d;
                }
            }
            float Li[N_D][N_D];
            for (int j = 0; j < N_D; j++)
                for (int i = 0; i < N_D; i++) {
                    if (i < j) { Li[i][j] = 0.0f; continue; }
                    float v = (i == j) ? 1.0f : 0.0f;
                    for (int k = j; k < i; k++) v -= L[i][k] * Li[k][j];
                    Li[i][j] = v / L[i][i];
                }
            float P[N_D][N_D];
            for (int i = 0; i < N_D; i++)
                for (int j = 0; j < N_D; j++) {
                    float v = 0.0f;
                    int k0 = (i > j) ? i : j;
                    for (int k = k0; k < N_D; k++) v += Li[k][i] * Li[k][j];
                    P[i][j] = v;
                }
            float w[N_D], quad = 0.0f;
            for (int i = 0; i < N_D; i++) {
                float v = 0.0f;
                for (int j = 0; j < N_D; j++) v += P[i][j] * mu[j];
                w[i] = v;
                quad += v * mu[i];
            }
            float kp = -0.5f * (logdet + (float)N_D * LOG2PI);
            float M = kp;
            #pragma unroll
            for (int o = 16; o > 0; o >>= 1)
                M = fmaxf(M, __shfl_xor_sync(0xffffffffu, M, o));
            if (tid == 0) g_M = M;

            float* Wc = (float*)g_W + tid * ROWF;
            // t-stage pairs, rows 0..8: even rows from j=i (incl diag),
            // odd rows from j=i+1 (diag split out). 25 pairs = 50 floats.
            int u = 0;
            for (int i = 0; i < 9; i++) {
                int jstart = (i % 2 == 0) ? i : i + 1;
                for (int j = jstart; j < N_D; j += 2) {
                    Wc[u++] = (i == j) ? (-0.5f * P[i][i]) : (-P[i][j]);
                    Wc[u++] = -P[i][j + 1];          // j+1 > i always here
                }
            }
            // u == 50: odd diagonals + row-9 diagonal
            Wc[50] = -0.5f * P[1][1];
            Wc[51] = -0.5f * P[3][3];
            Wc[52] = -0.5f * P[5][5];
            Wc[53] = -0.5f * P[7][7];
            Wc[54] = -0.5f * P[9][9];
            Wc[55] = 0.0f;
            for (int i = 0; i < N_D; i++) Wc[56 + i] = w[i];
            Wc[66] = (kp - 0.5f * quad) - M;         // K_c - M
            Wc[67] = 0.0f;
        }

        __shared__ float red[256];
        float acc = 0.0f;
        for (int i = tid; i < N_C; i += 256)
            acc += b_log_sig[i] - 0.5f * b_mu[i] * b_mu[i];
        for (int i = tid; i < N_C * N_T; i += 256)
            acc += beta_log_sig[i] - 0.5f * beta_mu[i] * beta_mu[i];
        red[tid] = acc;
        __syncthreads();
        for (int s2 = 128; s2 > 0; s2 >>= 1) {
            if (tid < s2) red[tid] += red[tid + s2];
            __syncthreads();
        }
        if (tid == 0) g_prior = red[0];
        return;
    }

    int warp = (blockIdx.x * blockDim.x + threadIdx.x) >> 5;
    int lane = threadIdx.x & 31;
    if (warp >= N_K * N_T) return;
    int k = warp >> 7;
    int t = warp & (N_T - 1);

    float yv  = __ldg(&y[k * N_T + t]);
    float lam = __ldg(&b_mu[lane]) + __ldg(&beta_mu[lane * N_T + t]) * yv;

    float m = lam;
    #pragma unroll
    for (int o = 16; o > 0; o >>= 1)
        m = fmaxf(m, __shfl_xor_sync(0xffffffffu, m, o));
    float e = __expf(lam - m);
    float ssum = e;
    #pragma unroll
    for (int o = 16; o > 0; o >>= 1)
        ssum += __shfl_xor_sync(0xffffffffu, ssum, o);

    g_logpi[warp * N_C + lane] = lam - m - __logf(ssum);
}

// ---------------------------------------------------------------------------
// Kernel 2: main — 2 spikes/thread, NESTED quad-form evaluation.
// Persistent per spike: 5 s-pairs + 9 splats + 3 square-pairs = 17 u64
// (no 28-pair feature vector) -> ~115 regs -> 4 CTAs/SM (16 warps; occupancy
// was the R13 limiter: all pipes ~44-51% at 12 warps).
// Per component: same 10-const/7-SMEM quad split as R13; 42 fma2/spike.
// ---------------------------------------------------------------------------
__global__ void __launch_bounds__(MAIN_BLOCK, 4)
main_kernel(const float* __restrict__ s,
            const int*   __restrict__ ks,
            const int*   __restrict__ ts,
            float*       __restrict__ out) {
    __shared__ __align__(16) u64 sW[N_C * ROWP];
    __shared__ float sred[MAIN_BLOCK];
    __shared__ unsigned int s_isLast;

    for (int i = threadIdx.x; i < N_C * ROWP; i += MAIN_BLOCK)
        sW[i] = g_W[i];
    __syncthreads();

    int nA = blockIdx.x * MAIN_BLOCK + threadIdx.x;
    float lsum = 0.0f;

    if (nA < N_HALF) {
        int nB = nA + N_HALF;

        float svA[N_D], svB[N_D];
        {
            const float2* pA = (const float2*)(s + (size_t)nA * N_D);
            const float2* pB = (const float2*)(s + (size_t)nB * N_D);
            #pragma unroll
            for (int p = 0; p < 5; p++) {
                float2 a = __ldg(&pA[p]); svA[2*p] = a.x; svA[2*p+1] = a.y;
                float2 b = __ldg(&pB[p]); svB[2*p] = b.x; svB[2*p+1] = b.y;
            }
        }

        // Persistent packed operands per spike: 5 s-pairs, 9 splats, 3 sq-pairs
        u64 spA[5], spB[5], splA[9], splB[9], sqA[3], sqB[3];
        #pragma unroll
        for (int p = 0; p < 5; p++) {
            spA[p] = pk2(svA[2*p], svA[2*p+1]);
            spB[p] = pk2(svB[2*p], svB[2*p+1]);
        }
        #pragma unroll
        for (int i = 0; i < 9; i++) {
            splA[i] = pk2(svA[i], svA[i]);
            splB[i] = pk2(svB[i], svB[i]);
        }
        sqA[0] = pk2(svA[1]*svA[1], svA[3]*svA[3]);
        sqA[1] = pk2(svA[5]*svA[5], svA[7]*svA[7]);
        sqA[2] = pk2(svA[9]*svA[9], 0.0f);
        sqB[0] = pk2(svB[1]*svB[1], svB[3]*svB[3]);
        sqB[1] = pk2(svB[5]*svB[5], svB[7]*svB[7]);
        sqB[2] = pk2(svB[9]*svB[9], 0.0f);

        const float4* lp4A = (const float4*)(g_logpi +
            ((size_t)(__ldg(&ks[nA]) * N_T + __ldg(&ts[nA]))) * N_C);
        const float4* lp4B = (const float4*)(g_logpi +
            ((size_t)(__ldg(&ks[nB]) * N_T + __ldg(&ts[nB]))) * N_C);

        const ulonglong2* cw2 = reinterpret_cast<const ulonglong2*>(c_W);

        float ssA = 0.0f, ssB = 0.0f;

        #pragma unroll 1
        for (int g = 0; g < 8; g++) {
            float4 lA = __ldg(&lp4A[g]);
            float4 lB = __ldg(&lp4B[g]);
            const float* lAf = (const float*)&lA;
            const float* lBf = (const float*)&lB;

            #pragma unroll
            for (int cc = 0; cc < 4; cc++) {
                int c = g * 4 + cc;
                const ulonglong2* w2 =
                    reinterpret_cast<const ulonglong2*>(sW + c * ROWP);
                const ulonglong2* cq = cw2 + c * ROWQ;

                u64 qA0 = 0ull, qA1 = 0ull, qB0 = 0ull, qB1 = 0ull;
                u64 tA, tB;
                ulonglong2 w;

                // row 0: pairs p0..p4 (sp0..sp4) -> q0
                w = cq[0];
                tA = mul2(w.x, spA[0]);  tB = mul2(w.x, spB[0]);
                fma2(tA, w.y, spA[1]);   fma2(tB, w.y, spB[1]);
                w = cq[1];
                fma2(tA, w.x, spA[2]);   fma2(tB, w.x, spB[2]);
                fma2(tA, w.y, spA[3]);   fma2(tB, w.y, spB[3]);
                w = cq[2];
                fma2(tA, w.x, spA[4]);   fma2(tB, w.x, spB[4]);
                fma2(qA0, splA[0], tA);  fma2(qB0, splB[0], tB);

                // row 1: p5..p8 (sp1..sp4) -> q1
                tA = mul2(w.y, spA[1]);  tB = mul2(w.y, spB[1]);
                w = cq[3];
                fma2(tA, w.x, spA[2]);   fma2(tB, w.x, spB[2]);
                fma2(tA, w.y, spA[3]);   fma2(tB, w.y, spB[3]);
                w = cq[4];
                fma2(tA, w.x, spA[4]);   fma2(tB, w.x, spB[4]);
                fma2(qA1, splA[1], tA);  fma2(qB1, splB[1], tB);

                // row 2: p9..p12 (sp1..sp4) -> q0
                tA = mul2(w.y, spA[1]);  tB = mul2(w.y, spB[1]);
                w = cq[5];
                fma2(tA, w.x, spA[2]);   fma2(tB, w.x, spB[2]);
                fma2(tA, w.y, spA[3]);   fma2(tB, w.y, spB[3]);
                w = cq[6];
                fma2(tA, w.x, spA[4]);   fma2(tB, w.x, spB[4]);
                fma2(qA0, splA[2], tA);  fma2(qB0, splB[2], tB);

                // row 3: p13..p15 (sp2..sp4) -> q1
                tA = mul2(w.y, spA[2]);  tB = mul2(w.y, spB[2]);
                w = cq[7];
                fma2(tA, w.x, spA[3]);   fma2(tB, w.x, spB[3]);
                fma2(tA, w.y, spA[4]);   fma2(tB, w.y, spB[4]);
                fma2(qA1, splA[3], tA);  fma2(qB1, splB[3], tB);

                // row 4: p16..p18 (sp2..sp4) -> q0
                w = cq[8];
                tA = mul2(w.x, spA[2]);  tB = mul2(w.x, spB[2]);
                fma2(tA, w.y, spA[3]);   fma2(tB, w.y, spB[3]);
                w = cq[9];
                fma2(tA, w.x, spA[4]);   fma2(tB, w.x, spB[4]);
                fma2(qA0, splA[4], tA);  fma2(qB0, splB[4], tB);

                // row 5: p19..p20 (sp3..sp4) -> q1   [const->SMEM boundary]
                tA = mul2(w.y, spA[3]);  tB = mul2(w.y, spB[3]);
                w = w2[10];
                fma2(tA, w.x, spA[4]);   fma2(tB, w.x, spB[4]);
                fma2(qA1, splA[5], tA);  fma2(qB1, splB[5], tB);

                // row 6: p21..p22 (sp3..sp4) -> q0
                tA = mul2(w.y, spA[3]);  tB = mul2(w.y, spB[3]);
                w = w2[11];
                fma2(tA, w.x, spA[4]);   fma2(tB, w.x, spB[4]);
                fma2(qA0, splA[6], tA);  fma2(qB0, splB[6], tB);

                // row 7: p23 (sp4) -> q1
                tA = mul2(w.y, spA[4]);  tB = mul2(w.y, spB[4]);
                fma2(qA1, splA[7], tA);  fma2(qB1, splB[7], tB);

                // row 8: p24 (sp4) -> q0
                w = w2[12];
                tA = mul2(w.x, spA[4]);  tB = mul2(w.x, spB[4]);
                fma2(qA0, splA[8], tA);  fma2(qB0, splB[8], tB);

                // diagonals: p25..p27 vs squares
                fma2(qA1, w.y, sqA[0]);  fma2(qB1, w.y, sqB[0]);
                w = w2[13];
                fma2(qA0, w.x, sqA[1]);  fma2(qB0, w.x, sqB[1]);
                fma2(qA1, w.y, sqA[2]);  fma2(qB1, w.y, sqB[2]);

                // linear: p28..p32 vs s-pairs
                w = w2[14];
                fma2(qA0, w.x, spA[0]);  fma2(qB0, w.x, spB[0]);
                fma2(qA1, w.y, spA[1]);  fma2(qB1, w.y, spB[1]);
                w = w2[15];
                fma2(qA0, w.x, spA[2]);  fma2(qB0, w.x, spB[2]);
                fma2(qA1, w.y, spA[3]);  fma2(qB1, w.y, spB[3]);
                w = w2[16];
                fma2(qA0, w.x, spA[4]);  fma2(qB0, w.x, spB[4]);
                float kc = upk(w.y).x;                 // K_c - M

                float2 qA = upk(add2(qA0, qA1));
                float2 qB = upk(add2(qB0, qB1));
                float logitA = (qA.x + qA.y) + kc + lAf[cc];   // <= ~0
                float logitB = (qB.x + qB.y) + kc + lBf[cc];
                ssA += __expf(logitA);
                ssB += __expf(logitB);
            }
        }
        lsum = __logf(fmaxf(ssA, 1e-30f)) + __logf(fmaxf(ssB, 1e-30f));
    }

    sred[threadIdx.x] = lsum;
    __syncthreads();
    #pragma unroll
    for (int s2 = MAIN_BLOCK / 2; s2 > 0; s2 >>= 1) {
        if (threadIdx.x < s2) sred[threadIdx.x] += sred[threadIdx.x + s2];
        __syncthreads();
    }
    if (threadIdx.x == 0) {
        g_partial[blockIdx.x] = sred[0];
        __threadfence();
        unsigned int prev = atomicAdd(&g_count, 1u);
        s_isLast = (prev == (unsigned int)(NBLOCKS - 1)) ? 1u : 0u;
    }
    __syncthreads();

    if (s_isLast) {
        __shared__ double dred[MAIN_BLOCK];
        const volatile float* vp = g_partial;
        double acc = 0.0;
        for (int i = threadIdx.x; i < NBLOCKS; i += MAIN_BLOCK)
            acc += (double)vp[i];
        dred[threadIdx.x] = acc;
        __syncthreads();
        for (int s2 = MAIN_BLOCK / 2; s2 > 0; s2 >>= 1) {
            if (threadIdx.x < s2) dred[threadIdx.x] += dred[threadIdx.x + s2];
            __syncthreads();
        }
        if (threadIdx.x == 0)
            out[0] = (float)(dred[0] + (double)g_prior
                             + (double)N_SPK * (double)g_M);
    }
}

// ---------------------------------------------------------------------------
extern "C" void kernel_launch(void* const* d_in, const int* in_sizes, int n_in,
                              void* d_out, int out_size) {
    const float* s            = (const float*)d_in[0];
    const float* y            = (const float*)d_in[1];
    const int*   ks           = (const int*)  d_in[2];
    const int*   ts           = (const int*)  d_in[3];
    const float* means        = (const float*)d_in[4];
    const float* covs         = (const float*)d_in[5];
    const float* b_mu         = (const float*)d_in[6];
    const float* b_log_sig    = (const float*)d_in[7];
    const float* beta_mu      = (const float*)d_in[8];
    const float* beta_log_sig = (const float*)d_in[9];

    logpi_setup_kernel<<<(N_K * N_T * 32) / 256 + 1, 256>>>(
        y, b_mu, beta_mu, means, covs, b_log_sig, beta_log_sig);

    // Mirror device-computed W into the constant bank (D2D node, capturable).
    void* g_W_addr = nullptr;
    cudaGetSymbolAddress(&g_W_addr, g_W);
    cudaMemcpyToSymbolAsync(c_W, g_W_addr, sizeof(u64) * N_C * ROWP, 0,
                            cudaMemcpyDeviceToDevice);

    main_kernel<<<NBLOCKS, MAIN_BLOCK>>>(s, ks, ts, (float*)d_out);
}